// round 5
// baseline (speedup 1.0000x reference)
#include <cuda_runtime.h>
#include <math.h>

// Problem constants
#define NCHUNK 32
#define NBATCH 64
#define HALF   128
#define SIZE   256
#define NROWS  (NCHUNK * NBATCH)          // 2048
#define C_SCALE 1e-4f
#define M_SCALE 1e-5f

// ---------------------------------------------------------------------------
// ydot kernel: one block per (chunk,batch) row. 128 threads.
// ydot[k]      = v[k]                       (k < 128)
// ydot[128+i]  = vdot[i]
// ---------------------------------------------------------------------------
__global__ void __launch_bounds__(HALF) ydot_kernel(
    const float* __restrict__ t,
    const float* __restrict__ y,
    const float* __restrict__ K,
    const float* __restrict__ C,
    const float* __restrict__ M,
    float* __restrict__ out)
{
    const int row = blockIdx.x;               // 0..2047
    const float* yr = y + (size_t)row * SIZE;
    float* o = out + (size_t)row * SIZE;

    __shared__ float su[HALF];
    __shared__ float sv[HALF];
    __shared__ float sf[HALF];

    const int i = threadIdx.x;                // 0..127
    const float u = yr[i];
    const float v = yr[HALF + i];
    su[i] = u;
    sv[i] = v;
    __syncthreads();

    const float Ki  = K[i];
    const float Csi = C[i] * C_SCALE;
    const float Msi = M[i] * M_SCALE;

    float fi = 0.0f;
    if (i < HALF - 1) {
        fi = Ki * (su[i + 1] - u) + Csi * (sv[i + 1] - v);
    }
    sf[i] = fi;
    __syncthreads();

    float num = fi;                           // f[i] term (0 for i==127)
    if (i > 0) num -= sf[i - 1];              // -f[i-1] term
    float vdot = num / Msi;
    if (i == HALF - 1) vdot -= (Ki * u + Csi * v) / Msi;
    if (i == 0)        vdot += sinf(t[row]) / Msi;

    o[i]        = v;
    o[HALF + i] = vdot;
}

// ---------------------------------------------------------------------------
// J kernel: J has shape (2048, 256, 256) and is a batch-broadcast of the
// constant matrix Jb. Each thread computes & stores one float4 (4 cols)
// with a streaming (.cs) store — J is write-once, never re-read.
// Jb structure:
//   r <  128 : row = e_{r+128} (identity in upper-right block)
//   r >= 128 : i = r-128; cols [0,128) = ku[i][:], cols [128,256) = kv[i][:]
//   ku[i][j] = ( j==i   : -(K[i] + (i>0 ? K[i-1] : 0)) / Ms[i]
//              | j==i+1 :  K[i]   / Ms[i]
//              | j==i-1 :  K[i-1] / Ms[i]
//              | else 0 )
//   kv identical with Cs = C*1e-4.
// Warp-uniform r (64 float4 per row, consecutive tids share r) keeps the
// big branch divergence-free; only ~1 warp per lower row touches K/C/M.
// ---------------------------------------------------------------------------
__global__ void __launch_bounds__(256) jmat_kernel(
    const float* __restrict__ K,
    const float* __restrict__ C,
    const float* __restrict__ M,
    float4* __restrict__ J)
{
    const unsigned q = blockIdx.x * 256u + threadIdx.x;  // < 33,554,432
    const unsigned m  = q & 16383u;        // index within one 256x256 matrix (float4 units)
    const int r  = (int)(m >> 6);          // row 0..255
    const int c0 = (int)(m & 63u) << 2;    // first of 4 columns

    float4 val = make_float4(0.f, 0.f, 0.f, 0.f);
    float* vv = reinterpret_cast<float*>(&val);

    if (r < HALF) {
        const int tc = r + HALF;           // identity column
        if ((tc & ~3) == c0) vv[tc & 3] = 1.0f;
    } else {
        const int i = r - HALF;
        const int j0 = c0 & (HALF - 1);
        // nonzero only if [j0, j0+3] intersects [i-1, i+1]
        if (j0 <= i + 1 && j0 + 3 >= i - 1) {
            const bool isv = (c0 >= HALF);
            const float rM = 1.0f / (M[i] * M_SCALE);
            const float a  = isv ? (C[i] * C_SCALE) : K[i];
            const float am = (i > 0) ? (isv ? (C[i - 1] * C_SCALE) : K[i - 1]) : 0.0f;
            const float diag = -(a + am) * rM;
            const float sup  = a * rM;     // j==i+1 (j<=127 bounds it naturally)
            const float sub  = am * rM;    // j==i-1 (am==0 kills i==0 case)
            #pragma unroll
            for (int kk = 0; kk < 4; kk++) {
                const int j = j0 + kk;
                vv[kk] = (j == i) ? diag : (j == i + 1) ? sup : (j == i - 1) ? sub : 0.0f;
            }
        }
    }
    __stcs(&J[q], val);                    // streaming store: evict-first in L2
}

// ---------------------------------------------------------------------------
// launch
// ---------------------------------------------------------------------------
extern "C" void kernel_launch(void* const* d_in, const int* in_sizes, int n_in,
                              void* d_out, int out_size)
{
    const float* t = (const float*)d_in[0];   // (32,64)
    const float* y = (const float*)d_in[1];   // (32,64,256)
    const float* K = (const float*)d_in[2];   // (128,)
    const float* C = (const float*)d_in[3];   // (128,)
    const float* M = (const float*)d_in[4];   // (128,)

    float* out = (float*)d_out;
    float* ydot = out;                                   // 2048*256 floats
    float4* J = (float4*)(out + (size_t)NROWS * SIZE);   // 2048*256*256 floats

    ydot_kernel<<<NROWS, HALF>>>(t, y, K, C, M, ydot);

    // 2048 * 256 * 256 / 4 = 33,554,432 float4 stores
    const unsigned total4 = (unsigned)NROWS * SIZE * (SIZE / 4);
    jmat_kernel<<<total4 / 256, 256>>>(K, C, M, J);
}

// round 8
// speedup vs baseline: 1.0093x; 1.0093x over previous
#include <cuda_runtime.h>
#include <math.h>

// Problem constants
#define NCHUNK 32
#define NBATCH 64
#define HALF   128
#define SIZE   256
#define NROWS  (NCHUNK * NBATCH)          // 2048
#define C_SCALE 1e-4f
#define M_SCALE 1e-5f

#define M_PER_MAT   (SIZE * SIZE / 4)     // 16384 float4 per matrix
#define BATCH_REP   8                     // batch copies per thread
#define JMAT_BLOCKS (M_PER_MAT * (NROWS / BATCH_REP) / 256)  // 16384
#define YDOT_BLOCKS (NROWS / 2)           // 1024 (2 rows per block)

// ---------------------------------------------------------------------------
// Fused kernel.
// Blocks [0, JMAT_BLOCKS):          J writer. Each thread owns one matrix
//   position m (4 cols) and stores the same float4 to BATCH_REP batch copies
//   (stride 256KB). Value computed once -> ALU amortized 8x vs 1 store/thread.
// Blocks [JMAT_BLOCKS, +YDOT_BLOCKS): ydot. 2 rows per 256-thread block.
// ---------------------------------------------------------------------------
__global__ void __launch_bounds__(256) fused_kernel(
    const float* __restrict__ t,
    const float* __restrict__ y,
    const float* __restrict__ K,
    const float* __restrict__ C,
    const float* __restrict__ M,
    float* __restrict__ ydot_out,
    float4* __restrict__ J)
{
    if (blockIdx.x < JMAT_BLOCKS) {
        // ------------------- J stream -------------------
        const unsigned g = blockIdx.x * 256u + threadIdx.x;   // < 4,194,304
        const unsigned m = g & (M_PER_MAT - 1u);   // matrix position (float4)
        const unsigned bg = g >> 14;               // batch group 0..255
        const int r  = (int)(m >> 6);              // row 0..255
        const int c0 = (int)(m & 63u) << 2;        // first of 4 columns

        float4 val = make_float4(0.f, 0.f, 0.f, 0.f);
        float* vv = reinterpret_cast<float*>(&val);

        if (r < HALF) {
            const int tc = r + HALF;               // identity column
            if ((tc & ~3) == c0) vv[tc & 3] = 1.0f;
        } else {
            const int i = r - HALF;
            const int j0 = c0 & (HALF - 1);
            if (j0 <= i + 1 && j0 + 3 >= i - 1) {
                const bool isv = (c0 >= HALF);
                const float rM = 1.0f / (M[i] * M_SCALE);
                const float a  = isv ? (C[i] * C_SCALE) : K[i];
                const float am = (i > 0) ? (isv ? (C[i - 1] * C_SCALE) : K[i - 1]) : 0.0f;
                const float diag = -(a + am) * rM;
                const float sup  = a * rM;
                const float sub  = am * rM;
                #pragma unroll
                for (int kk = 0; kk < 4; kk++) {
                    const int j = j0 + kk;
                    vv[kk] = (j == i) ? diag : (j == i + 1) ? sup : (j == i - 1) ? sub : 0.0f;
                }
            }
        }

        float4* p = J + (size_t)bg * BATCH_REP * M_PER_MAT + m;
        #pragma unroll
        for (int rep = 0; rep < BATCH_REP; rep++) {
            __stcs(p, val);
            p += M_PER_MAT;
        }
    } else {
        // ------------------- ydot -------------------
        const int sub = threadIdx.x >> 7;              // 0 or 1: which row
        const int i   = threadIdx.x & (HALF - 1);      // 0..127
        const int row = (int)(blockIdx.x - JMAT_BLOCKS) * 2 + sub;

        const float* yr = y + (size_t)row * SIZE;
        float* o = ydot_out + (size_t)row * SIZE;

        __shared__ float su[2][HALF];
        __shared__ float sv[2][HALF];
        __shared__ float sf[2][HALF];

        const float u = yr[i];
        const float v = yr[HALF + i];
        su[sub][i] = u;
        sv[sub][i] = v;
        __syncthreads();

        const float Ki  = K[i];
        const float Csi = C[i] * C_SCALE;
        const float Msi = M[i] * M_SCALE;

        float fi = 0.0f;
        if (i < HALF - 1) {
            fi = Ki * (su[sub][i + 1] - u) + Csi * (sv[sub][i + 1] - v);
        }
        sf[sub][i] = fi;
        __syncthreads();

        float num = fi;                               // f[i] term (0 for i==127)
        if (i > 0) num -= sf[sub][i - 1];             // -f[i-1]
        float vdot = num / Msi;
        if (i == HALF - 1) vdot -= (Ki * u + Csi * v) / Msi;
        if (i == 0)        vdot += sinf(t[row]) / Msi;

        o[i]        = v;
        o[HALF + i] = vdot;
    }
}

// ---------------------------------------------------------------------------
// launch
// ---------------------------------------------------------------------------
extern "C" void kernel_launch(void* const* d_in, const int* in_sizes, int n_in,
                              void* d_out, int out_size)
{
    const float* t = (const float*)d_in[0];   // (32,64)
    const float* y = (const float*)d_in[1];   // (32,64,256)
    const float* K = (const float*)d_in[2];   // (128,)
    const float* C = (const float*)d_in[3];   // (128,)
    const float* M = (const float*)d_in[4];   // (128,)

    float* out = (float*)d_out;
    float* ydot = out;                                   // 2048*256 floats
    float4* J = (float4*)(out + (size_t)NROWS * SIZE);   // 2048*256*256 floats

    fused_kernel<<<JMAT_BLOCKS + YDOT_BLOCKS, 256>>>(t, y, K, C, M, ydot, J);
}

// round 12
// speedup vs baseline: 1.0131x; 1.0038x over previous
#include <cuda_runtime.h>
#include <math.h>

// Problem constants
#define NCHUNK 32
#define NBATCH 64
#define HALF   128
#define SIZE   256
#define NROWS  (NCHUNK * NBATCH)          // 2048
#define C_SCALE 1e-4f
#define M_SCALE 1e-5f

#define M_PER_MAT   (SIZE * SIZE / 4)     // 16384 float4 per matrix
#define YDOT_BLOCKS (NROWS / 2)           // 1024 (2 rows per block)
#define JMAT_BLOCKS (M_PER_MAT * NROWS / 256)   // 131072 (1 float4 per thread)

// ---------------------------------------------------------------------------
// Fused kernel, ydot-first ordering.
// Blocks [0, YDOT_BLOCKS):  ydot. 2 rows per 256-thread block. Scheduled
//   first so the small input loads hide under store-stream ramp-up.
// Blocks [YDOT_BLOCKS, +JMAT_BLOCKS): J writer, one float4 per thread,
//   globally LINEAR store stream (consecutive CTAs -> consecutive 4KB
//   chunks) for maximal HBM write locality. ALU recompute per position is
//   cheap: issue was at 11.7% with replication, 70.3% without -- headroom.
// ---------------------------------------------------------------------------
__global__ void __launch_bounds__(256) fused_kernel(
    const float* __restrict__ t,
    const float* __restrict__ y,
    const float* __restrict__ K,
    const float* __restrict__ C,
    const float* __restrict__ M,
    float* __restrict__ ydot_out,
    float4* __restrict__ J)
{
    if (blockIdx.x >= YDOT_BLOCKS) {
        // ------------------- J stream (linear) -------------------
        const unsigned q = (blockIdx.x - YDOT_BLOCKS) * 256u + threadIdx.x; // < 33,554,432
        const unsigned m = q & (M_PER_MAT - 1u);   // position within one matrix
        const int r  = (int)(m >> 6);              // row 0..255
        const int c0 = (int)(m & 63u) << 2;        // first of 4 columns

        float4 val = make_float4(0.f, 0.f, 0.f, 0.f);
        float* vv = reinterpret_cast<float*>(&val);

        if (r < HALF) {
            const int tc = r + HALF;               // identity column
            if ((tc & ~3) == c0) vv[tc & 3] = 1.0f;
        } else {
            const int i = r - HALF;
            const int j0 = c0 & (HALF - 1);
            if (j0 <= i + 1 && j0 + 3 >= i - 1) {
                const bool isv = (c0 >= HALF);
                const float rM = 1.0f / (M[i] * M_SCALE);
                const float a  = isv ? (C[i] * C_SCALE) : K[i];
                const float am = (i > 0) ? (isv ? (C[i - 1] * C_SCALE) : K[i - 1]) : 0.0f;
                const float diag = -(a + am) * rM;
                const float sup  = a * rM;
                const float sub  = am * rM;
                #pragma unroll
                for (int kk = 0; kk < 4; kk++) {
                    const int j = j0 + kk;
                    vv[kk] = (j == i) ? diag : (j == i + 1) ? sup : (j == i - 1) ? sub : 0.0f;
                }
            }
        }
        __stcs(&J[q], val);                        // streaming store
    } else {
        // ------------------- ydot -------------------
        const int sub = threadIdx.x >> 7;              // 0 or 1: which row
        const int i   = threadIdx.x & (HALF - 1);      // 0..127
        const int row = (int)blockIdx.x * 2 + sub;

        const float* yr = y + (size_t)row * SIZE;
        float* o = ydot_out + (size_t)row * SIZE;

        __shared__ float su[2][HALF];
        __shared__ float sv[2][HALF];
        __shared__ float sf[2][HALF];

        const float u = yr[i];
        const float v = yr[HALF + i];
        su[sub][i] = u;
        sv[sub][i] = v;
        __syncthreads();

        const float Ki  = K[i];
        const float Csi = C[i] * C_SCALE;
        const float Msi = M[i] * M_SCALE;

        float fi = 0.0f;
        if (i < HALF - 1) {
            fi = Ki * (su[sub][i + 1] - u) + Csi * (sv[sub][i + 1] - v);
        }
        sf[sub][i] = fi;
        __syncthreads();

        float num = fi;                               // f[i] term (0 for i==127)
        if (i > 0) num -= sf[sub][i - 1];             // -f[i-1]
        float vdot = num / Msi;
        if (i == HALF - 1) vdot -= (Ki * u + Csi * v) / Msi;
        if (i == 0)        vdot += sinf(t[row]) / Msi;

        o[i]        = v;
        o[HALF + i] = vdot;
    }
}

// ---------------------------------------------------------------------------
// launch
// ---------------------------------------------------------------------------
extern "C" void kernel_launch(void* const* d_in, const int* in_sizes, int n_in,
                              void* d_out, int out_size)
{
    const float* t = (const float*)d_in[0];   // (32,64)
    const float* y = (const float*)d_in[1];   // (32,64,256)
    const float* K = (const float*)d_in[2];   // (128,)
    const float* C = (const float*)d_in[3];   // (128,)
    const float* M = (const float*)d_in[4];   // (128,)

    float* out = (float*)d_out;
    float* ydot = out;                                   // 2048*256 floats
    float4* J = (float4*)(out + (size_t)NROWS * SIZE);   // 2048*256*256 floats

    fused_kernel<<<YDOT_BLOCKS + JMAT_BLOCKS, 256>>>(t, y, K, C, M, ydot, J);
}